// round 13
// baseline (speedup 1.0000x reference)
#include <cuda_runtime.h>
#include <cuda_fp16.h>
#include <cstdint>
#include <math.h>

#define D_IN  256
#define D_H   512
#define D_OUT 256
#define NB    8
#define ROWS  (9 * 32768)

#define MT  128    // CTA M tile
#define NTT 128    // CTA N tile
#define KC  64     // K chunk (halves) = 128 B/row

// Scratch (allocation-free rule)
__device__ __half g_Xn [(size_t)ROWS * D_IN];
__device__ __half g_H  [(size_t)ROWS * D_H];
__device__ __half g_F  [(size_t)ROWS * D_OUT];   // fp16 glue buffer
__device__ __half g_W1T[(size_t)D_H * D_IN];     // [N=512][K=256]
__device__ __half g_W2T[(size_t)D_OUT * D_H];    // [N=256][K=512]

// ---------------------------------------------------------------------------
__device__ __forceinline__ uint32_t smem_u32(const void* p) {
    uint32_t a;
    asm("{ .reg .u64 t; cvta.to.shared.u64 t, %1; cvt.u32.u64 %0, t; }" : "=r"(a) : "l"(p));
    return a;
}
__device__ __forceinline__ void cpa16(uint32_t s, const void* g) {
    asm volatile("cp.async.cg.shared.global [%0], [%1], 16;" :: "r"(s), "l"(g));
}
__device__ __forceinline__ void ldsm4(uint32_t* r, uint32_t addr) {
    asm volatile("ldmatrix.sync.aligned.m8n8.x4.shared.b16 {%0,%1,%2,%3}, [%4];"
                 : "=r"(r[0]), "=r"(r[1]), "=r"(r[2]), "=r"(r[3]) : "r"(addr));
}
__device__ __forceinline__ void mma_f16(float* c, const uint32_t* a, const uint32_t* b) {
    asm volatile("mma.sync.aligned.m16n8k16.row.col.f32.f16.f16.f32 "
                 "{%0,%1,%2,%3}, {%4,%5,%6,%7}, {%8,%9}, {%0,%1,%2,%3};"
                 : "+f"(c[0]), "+f"(c[1]), "+f"(c[2]), "+f"(c[3])
                 : "r"(a[0]), "r"(a[1]), "r"(a[2]), "r"(a[3]), "r"(b[0]), "r"(b[1]));
}

// SMEM: 3 stages x (A 16K + B 16K) = 96 KB dynamic (tiles: 128 rows x 128 B)
#define TILE_BYTES  (MT * KC * 2)        // 16384
#define STAGE_BYTES (2 * TILE_BYTES)     // 32768
#define SM_TOTAL    (3 * STAGE_BYTES)    // 98304

// ---------------------------------------------------------------------------
// fp16 mma.sync GEMM (fp32 accum): CTA 128x128, 4 warps in 2x2 grid of
// 64x64 warp tiles, 3-stage cp.async ring with ONE barrier per K-chunk,
// 2 CTAs/SM. fp16 output. C = A[M,K] @ Bt[N,K]^T + bias (opt ReLU).
//
// Ring invariant at iter kt: compute stage kt%3; chunks kt+1, kt+2 in
// flight to stages (kt+1)%3, (kt+2)%3. The single __syncthreads after
// wait_group(1) orders all warps' reads of stage (kt-1)%3 (== (kt+2)%3)
// before it is overwritten. cp.async groups complete in commit order, so
// uniform empty-commits keep wait_group(1) exact at the tail.
// ---------------------------------------------------------------------------
__global__ void __launch_bounds__(128, 2) tc_gemm(
    const __half* __restrict__ A, const __half* __restrict__ Bt,
    const float* __restrict__ bias, __half* __restrict__ C,
    int K, int ldc, int relu)
{
    extern __shared__ char smem[];
    uint32_t sb = smem_u32(smem);
    const int tid = threadIdx.x, wid = tid >> 5, lane = tid & 31;
    const int row0 = blockIdx.y * MT;
    const int n0   = blockIdx.x * NTT;

    uint32_t aoff[3], boff[3];
#pragma unroll
    for (int s = 0; s < 3; s++) {
        aoff[s] = sb + s * STAGE_BYTES;
        boff[s] = sb + s * STAGE_BYTES + TILE_BYTES;
    }

    // loader: 128 rows x 8 16B-blocks per tile; 128 threads x 8 iters each
    const int lr = tid >> 3;          // base row 0..15, stride 16
    const int lc = tid & 7;           // 16B block (8 halves)
    const __half* Abase = A  + (size_t)row0 * K + lc * 8;
    const __half* Bbase = Bt + (size_t)n0   * K + lc * 8;

    auto load_chunk = [&](int kt, int bi) {
        const __half* Ap = Abase + kt * KC;
        const __half* Bp = Bbase + kt * KC;
#pragma unroll
        for (int i = 0; i < 8; i++) {
            int r = lr + i * 16;
            uint32_t so = (uint32_t)(r * 128 + ((lc ^ (r & 7)) << 4));
            cpa16(aoff[bi] + so, Ap + (size_t)r * K);
            cpa16(boff[bi] + so, Bp + (size_t)r * K);
        }
        asm volatile("cp.async.commit_group;" ::: "memory");
    };

    const int wm = (wid >> 1) * 64;   // warp M offset
    const int wn = (wid & 1) * 64;    // warp N offset

    const int q = lane >> 3;
    const int arow_base = wm + (q & 1) * 8 + (lane & 7);
    const int acb_add   = q >> 1;
    const int brow_base = wn + (q >> 1) * 8 + (lane & 7);
    const int bcb_add   = q & 1;

    float acc[4][8][4];
#pragma unroll
    for (int i = 0; i < 4; i++)
#pragma unroll
        for (int j = 0; j < 8; j++)
#pragma unroll
            for (int c = 0; c < 4; c++) acc[i][j][c] = 0.0f;

    const int nkt = K / KC;

    // prologue: 2 chunks in flight
    load_chunk(0, 0);
    if (nkt > 1) load_chunk(1, 1);
    else         asm volatile("cp.async.commit_group;" ::: "memory");

    int cur = 0, nxt = 2;
    for (int kt = 0; kt < nkt; kt++) {
        // chunk kt ready when <=1 newer group pending (in-order completion)
        asm volatile("cp.async.wait_group 1;" ::: "memory");
        __syncthreads();   // chunk kt visible; stage 'nxt' free (read done @ kt-1)

        if (kt + 2 < nkt) load_chunk(kt + 2, nxt);
        else asm volatile("cp.async.commit_group;" ::: "memory");

#pragma unroll
        for (int s = 0; s < 4; s++) {          // 4 x k16 substeps
            uint32_t af[4][4], bf[4][4];
#pragma unroll
            for (int i = 0; i < 4; i++) {
                int r = arow_base + i * 16;
                int cb = (2 * s + acb_add) ^ (r & 7);
                ldsm4(af[i], aoff[cur] + (uint32_t)(r * 128 + cb * 16));
            }
#pragma unroll
            for (int j2 = 0; j2 < 4; j2++) {
                int r = brow_base + j2 * 16;
                int cb = (2 * s + bcb_add) ^ (r & 7);
                ldsm4(bf[j2], boff[cur] + (uint32_t)(r * 128 + cb * 16));
            }
#pragma unroll
            for (int i = 0; i < 4; i++)
#pragma unroll
                for (int j = 0; j < 8; j++)
                    mma_f16(acc[i][j], af[i], &bf[j >> 1][(j & 1) * 2]);
        }

        cur = (cur == 2) ? 0 : cur + 1;
        nxt = (nxt == 2) ? 0 : nxt + 1;
    }

    // epilogue (fp16 store)
    const int g = lane >> 2, cpair = (lane & 3) * 2;
#pragma unroll
    for (int j = 0; j < 8; j++) {
        int col = n0 + wn + j * 8 + cpair;
        float b0 = __ldg(bias + col), b1 = __ldg(bias + col + 1);
#pragma unroll
        for (int i = 0; i < 4; i++) {
            int r = row0 + wm + i * 16 + g;
            float v0 = acc[i][j][0] + b0, v1 = acc[i][j][1] + b1;
            float v2 = acc[i][j][2] + b0, v3 = acc[i][j][3] + b1;
            if (relu) {
                v0 = fmaxf(v0, 0.0f); v1 = fmaxf(v1, 0.0f);
                v2 = fmaxf(v2, 0.0f); v3 = fmaxf(v3, 0.0f);
            }
            *reinterpret_cast<__half2*>(C + (size_t)r * ldc + col)
                = __floats2half2_rn(v0, v1);
            *reinterpret_cast<__half2*>(C + (size_t)(r + 8) * ldc + col)
                = __floats2half2_rn(v2, v3);
        }
    }
}

// ---------------------------------------------------------------------------
// Weight transpose to fp16: WT[c][r] = h(W[r][c])
// ---------------------------------------------------------------------------
__global__ __launch_bounds__(256) void transpose_kernel(
    const float* __restrict__ W, __half* __restrict__ WT, int R, int Cn)
{
    __shared__ float t[32][33];
    int bx = blockIdx.x * 32, by = blockIdx.y * 32;
    int x = threadIdx.x & 31, y = threadIdx.x >> 5;
#pragma unroll
    for (int i = 0; i < 32; i += 8)
        t[y + i][x] = W[(size_t)(by + y + i) * Cn + bx + x];
    __syncthreads();
#pragma unroll
    for (int i = 0; i < 32; i += 8)
        WT[(size_t)(bx + y + i) * R + by + x] = __float2half_rn(t[x][y + i]);
}

// ---------------------------------------------------------------------------
// LayerNorm (one warp/row), fp16 output
// ---------------------------------------------------------------------------
__global__ __launch_bounds__(256) void ln_kernel(
    const float* __restrict__ state, const float* __restrict__ nbrs,
    const float* __restrict__ gamma, const float* __restrict__ beta,
    __half* __restrict__ Xn, int B)
{
    int row  = blockIdx.x * 8 + (threadIdx.x >> 5);
    int lane = threadIdx.x & 31;
    const float* x = (row < B) ? state + (size_t)row * D_IN
                               : nbrs + (size_t)(row - B) * D_IN;
    float4 v0 = ((const float4*)x)[lane];
    float4 v1 = ((const float4*)x)[lane + 32];

    float s  = v0.x + v0.y + v0.z + v0.w + v1.x + v1.y + v1.z + v1.w;
    float ss = v0.x*v0.x + v0.y*v0.y + v0.z*v0.z + v0.w*v0.w
             + v1.x*v1.x + v1.y*v1.y + v1.z*v1.z + v1.w*v1.w;
#pragma unroll
    for (int o = 16; o; o >>= 1) {
        s  += __shfl_xor_sync(0xFFFFFFFFu, s,  o);
        ss += __shfl_xor_sync(0xFFFFFFFFu, ss, o);
    }
    float mu   = s * (1.0f / D_IN);
    float var  = ss * (1.0f / D_IN) - mu * mu;
    float rstd = rsqrtf(var + 1e-5f);

    float4 g0 = ((const float4*)gamma)[lane];
    float4 g1 = ((const float4*)gamma)[lane + 32];
    float4 be0 = ((const float4*)beta)[lane];
    float4 be1 = ((const float4*)beta)[lane + 32];

    __half2 h0 = __floats2half2_rn((v0.x - mu) * rstd * g0.x + be0.x,
                                   (v0.y - mu) * rstd * g0.y + be0.y);
    __half2 h1 = __floats2half2_rn((v0.z - mu) * rstd * g0.z + be0.z,
                                   (v0.w - mu) * rstd * g0.w + be0.w);
    __half2 h2 = __floats2half2_rn((v1.x - mu) * rstd * g1.x + be1.x,
                                   (v1.y - mu) * rstd * g1.y + be1.y);
    __half2 h3 = __floats2half2_rn((v1.z - mu) * rstd * g1.z + be1.z,
                                   (v1.w - mu) * rstd * g1.w + be1.w);

    __half* dst = Xn + (size_t)row * D_IN;
    uint2 w0, w1;
    w0.x = *(uint32_t*)&h0;  w0.y = *(uint32_t*)&h1;
    w1.x = *(uint32_t*)&h2;  w1.y = *(uint32_t*)&h3;
    ((uint2*)dst)[lane]      = w0;
    ((uint2*)(dst + 128))[lane] = w1;
}

// ---------------------------------------------------------------------------
// Attention aggregation (one warp/batch element), fp16 F, fp32 math/output.
// ---------------------------------------------------------------------------
__global__ __launch_bounds__(256) void attn_kernel(
    const __half* __restrict__ F, const float* __restrict__ aw,
    const float* __restrict__ ab_ptr, float* __restrict__ out, int B)
{
    int b    = blockIdx.x * 8 + (threadIdx.x >> 5);
    int lane = threadIdx.x & 31;
    float ab = ab_ptr[0];

    float4 w0 = ((const float4*)aw)[lane * 2];
    float4 w1 = ((const float4*)aw)[lane * 2 + 1];

    uint4 lv = ((const uint4*)(F + (size_t)b * D_OUT))[lane];
    float2 l0 = __half22float2(*(__half2*)&lv.x);
    float2 l1 = __half22float2(*(__half2*)&lv.y);
    float2 l2 = __half22float2(*(__half2*)&lv.z);
    float2 l3 = __half22float2(*(__half2*)&lv.w);

    uint4 nf[NB];
    float sc[NB];
#pragma unroll
    for (int n = 0; n < NB; n++) {
        nf[n] = ((const uint4*)(F + ((size_t)(1 + n) * B + b) * D_OUT))[lane];
        float2 a0 = __half22float2(*(__half2*)&nf[n].x);
        float2 a1 = __half22float2(*(__half2*)&nf[n].y);
        float2 a2 = __half22float2(*(__half2*)&nf[n].z);
        float2 a3 = __half22float2(*(__half2*)&nf[n].w);
        float d = a0.x * w0.x + a0.y * w0.y + a1.x * w0.z + a1.y * w0.w
                + a2.x * w1.x + a2.y * w1.y + a3.x * w1.z + a3.y * w1.w;
#pragma unroll
        for (int o = 16; o; o >>= 1) d += __shfl_xor_sync(0xFFFFFFFFu, d, o);
        sc[n] = d + ab;
    }

    float mx = sc[0];
#pragma unroll
    for (int n = 1; n < NB; n++) mx = fmaxf(mx, sc[n]);
    float se = 0.0f;
#pragma unroll
    for (int n = 0; n < NB; n++) { sc[n] = expf(sc[n] - mx); se += sc[n]; }
    float inv = 1.0f / se;

    float o0 = l0.x, o1 = l0.y, o2 = l1.x, o3 = l1.y;
    float o4 = l2.x, o5 = l2.y, o6 = l3.x, o7 = l3.y;
#pragma unroll
    for (int n = 0; n < NB; n++) {
        float wn = sc[n] * inv;
        float2 a0 = __half22float2(*(__half2*)&nf[n].x);
        float2 a1 = __half22float2(*(__half2*)&nf[n].y);
        float2 a2 = __half22float2(*(__half2*)&nf[n].z);
        float2 a3 = __half22float2(*(__half2*)&nf[n].w);
        o0 = fmaf(wn, a0.x, o0);  o1 = fmaf(wn, a0.y, o1);
        o2 = fmaf(wn, a1.x, o2);  o3 = fmaf(wn, a1.y, o3);
        o4 = fmaf(wn, a2.x, o4);  o5 = fmaf(wn, a2.y, o5);
        o6 = fmaf(wn, a3.x, o6);  o7 = fmaf(wn, a3.y, o7);
    }
    float* dst = out + (size_t)b * D_OUT;
    float4 r0 = { o0, o1, o2, o3 }, r1 = { o4, o5, o6, o7 };
    ((float4*)dst)[lane * 2]     = r0;
    ((float4*)dst)[lane * 2 + 1] = r1;
}

// ---------------------------------------------------------------------------
extern "C" void kernel_launch(void* const* d_in, const int* in_sizes, int n_in,
                              void* d_out, int out_size)
{
    const float* state = (const float*)d_in[0];
    const float* nbrs  = (const float*)d_in[1];
    const float* gamma = (const float*)d_in[2];
    const float* beta  = (const float*)d_in[3];
    const float* W1    = (const float*)d_in[4];
    const float* b1    = (const float*)d_in[5];
    const float* W2    = (const float*)d_in[6];
    const float* b2    = (const float*)d_in[7];
    const float* aw    = (const float*)d_in[8];
    const float* ab    = (const float*)d_in[9];
    float* out = (float*)d_out;

    int B = in_sizes[0] / D_IN;   // 32768
    int R = 9 * B;                // 294912

    __half *Xn, *H, *F, *W1T, *W2T;
    cudaGetSymbolAddress((void**)&Xn,  g_Xn);
    cudaGetSymbolAddress((void**)&H,   g_H);
    cudaGetSymbolAddress((void**)&F,   g_F);
    cudaGetSymbolAddress((void**)&W1T, g_W1T);
    cudaGetSymbolAddress((void**)&W2T, g_W2T);

    cudaFuncSetAttribute(tc_gemm, cudaFuncAttributeMaxDynamicSharedMemorySize, SM_TOTAL);

    transpose_kernel<<<dim3(D_H / 32,  D_IN / 32), 256>>>(W1, W1T, D_IN, D_H);
    transpose_kernel<<<dim3(D_OUT / 32, D_H / 32), 256>>>(W2, W2T, D_H, D_OUT);
    ln_kernel<<<R / 8, 256>>>(state, nbrs, gamma, beta, Xn, B);

    // H = h(relu(Xn @ W1 + b1))
    tc_gemm<<<dim3(D_H / NTT,  R / MT), 128, SM_TOTAL>>>(Xn, W1T, b1, H, D_IN, D_H, 1);
    // F = h(H @ W2 + b2)
    tc_gemm<<<dim3(D_OUT / NTT, R / MT), 128, SM_TOTAL>>>(H, W2T, b2, F, D_H, D_OUT, 0);

    attn_kernel<<<B / 8, 256>>>(F, aw, ab, out, B);
}

// round 14
// speedup vs baseline: 1.0811x; 1.0811x over previous
#include <cuda_runtime.h>
#include <cuda_fp16.h>
#include <cstdint>
#include <math.h>

#define D_IN  256
#define D_H   512
#define D_OUT 256
#define NB    8
#define ROWS  (9 * 32768)

#define MT  128    // M tile (per m-step)
#define NTT 128    // CTA N tile
#define KC  64     // K chunk (halves) = 128 B/row
#define MSTEPS 4   // m-tiles per CTA in gemm1

// Scratch (allocation-free rule)
__device__ __half g_Xn [(size_t)ROWS * D_IN];
__device__ __half g_H  [(size_t)ROWS * D_H];
__device__ __half g_F  [(size_t)ROWS * D_OUT];   // fp16 glue buffer
__device__ __half g_W1T[(size_t)D_H * D_IN];     // [N=512][K=256]
__device__ __half g_W2T[(size_t)D_OUT * D_H];    // [N=256][K=512]

// ---------------------------------------------------------------------------
__device__ __forceinline__ uint32_t smem_u32(const void* p) {
    uint32_t a;
    asm("{ .reg .u64 t; cvta.to.shared.u64 t, %1; cvt.u32.u64 %0, t; }" : "=r"(a) : "l"(p));
    return a;
}
__device__ __forceinline__ void cpa16(uint32_t s, const void* g) {
    asm volatile("cp.async.cg.shared.global [%0], [%1], 16;" :: "r"(s), "l"(g));
}
__device__ __forceinline__ void ldsm4(uint32_t* r, uint32_t addr) {
    asm volatile("ldmatrix.sync.aligned.m8n8.x4.shared.b16 {%0,%1,%2,%3}, [%4];"
                 : "=r"(r[0]), "=r"(r[1]), "=r"(r[2]), "=r"(r[3]) : "r"(addr));
}
__device__ __forceinline__ void mma_f16(float* c, const uint32_t* a, const uint32_t* b) {
    asm volatile("mma.sync.aligned.m16n8k16.row.col.f32.f16.f16.f32 "
                 "{%0,%1,%2,%3}, {%4,%5,%6,%7}, {%8,%9}, {%0,%1,%2,%3};"
                 : "+f"(c[0]), "+f"(c[1]), "+f"(c[2]), "+f"(c[3])
                 : "r"(a[0]), "r"(a[1]), "r"(a[2]), "r"(a[3]), "r"(b[0]), "r"(b[1]));
}

#define TILE_BYTES  (MT * KC * 2)        // 16384 (one 128-row x 128B tile)

// ===========================================================================
// GEMM1, B-resident: CTA handles [4 m-tiles x 128] rows x 128 cols.
// smem: B resident 64 KB (4 K-chunks) + A 2-stage ring 32 KB = 96 KB,
// 2 CTAs/SM. Flat loop over 16 A-chunks (mt = c>>2, kt = c&3), R12-style
// 2-sync double buffer; epilogue per m-tile inside the loop.
// ===========================================================================
#define G1_SMEM (4 * TILE_BYTES + 2 * TILE_BYTES)   // 98304

__global__ void __launch_bounds__(128, 2) tc_gemm1(
    const __half* __restrict__ A, const __half* __restrict__ Bt,
    const float* __restrict__ bias, __half* __restrict__ C)
{
    extern __shared__ char smem[];
    uint32_t sb = smem_u32(smem);
    const int tid = threadIdx.x, wid = tid >> 5, lane = tid & 31;
    const int rowbase = blockIdx.y * (MSTEPS * MT);
    const int n0      = blockIdx.x * NTT;

    const uint32_t bres    = sb;                       // B: 4 chunks x 16 KB
    const uint32_t aoff[2] = { sb + 4 * TILE_BYTES, sb + 5 * TILE_BYTES };

    const int lr = tid >> 3;          // base row 0..15, stride 16
    const int lc = tid & 7;           // 16B block (8 halves)
    const __half* Bbase = Bt + (size_t)n0 * D_IN + lc * 8;
    const __half* Abase = A + (size_t)rowbase * D_IN + lc * 8;

    // ---- prologue: resident B (one group), then A chunks 0,1 --------------
    {
#pragma unroll
        for (int kt = 0; kt < 4; kt++) {
            const __half* Bp = Bbase + kt * KC;
#pragma unroll
            for (int i = 0; i < 8; i++) {
                int r = lr + i * 16;
                uint32_t so = (uint32_t)(r * 128 + ((lc ^ (r & 7)) << 4));
                cpa16(bres + kt * TILE_BYTES + so, Bp + (size_t)r * D_IN);
            }
        }
        asm volatile("cp.async.commit_group;" ::: "memory");
    }
    auto loadA = [&](int c, int bi) {   // chunk c: mt=c>>2, kt=c&3
        const __half* Ap = Abase + (size_t)(c >> 2) * MT * D_IN + (c & 3) * KC;
#pragma unroll
        for (int i = 0; i < 8; i++) {
            int r = lr + i * 16;
            uint32_t so = (uint32_t)(r * 128 + ((lc ^ (r & 7)) << 4));
            cpa16(aoff[bi] + so, Ap + (size_t)r * D_IN);
        }
        asm volatile("cp.async.commit_group;" ::: "memory");
    };
    loadA(0, 0);

    const int wm = (wid >> 1) * 64;   // warp M offset
    const int wn = (wid & 1) * 64;    // warp N offset
    const int q = lane >> 3;
    const int arow_base = wm + (q & 1) * 8 + (lane & 7);
    const int acb_add   = q >> 1;
    const int brow_base = wn + (q >> 1) * 8 + (lane & 7);
    const int bcb_add   = q & 1;
    const int g = lane >> 2, cpair = (lane & 3) * 2;

    float acc[4][8][4];
#pragma unroll
    for (int i = 0; i < 4; i++)
#pragma unroll
        for (int j = 0; j < 8; j++)
#pragma unroll
            for (int c = 0; c < 4; c++) acc[i][j][c] = 0.0f;

    const int NCH = MSTEPS * 4;       // 16 A-chunks
    for (int c = 0; c < NCH; c++) {
        int b = c & 1;
        if (c + 1 < NCH) {
            loadA(c + 1, b ^ 1);
            asm volatile("cp.async.wait_group 1;" ::: "memory");
        } else {
            asm volatile("cp.async.wait_group 0;" ::: "memory");
        }
        __syncthreads();   // A chunk c visible (B complete since c=0); WAR ok

        const uint32_t bchunk = bres + (uint32_t)(c & 3) * TILE_BYTES;
#pragma unroll
        for (int s = 0; s < 4; s++) {          // 4 x k16 substeps
            uint32_t af[4][4], bf[4][4];
#pragma unroll
            for (int i = 0; i < 4; i++) {
                int r = arow_base + i * 16;
                int cb = (2 * s + acb_add) ^ (r & 7);
                ldsm4(af[i], aoff[b] + (uint32_t)(r * 128 + cb * 16));
            }
#pragma unroll
            for (int j2 = 0; j2 < 4; j2++) {
                int r = brow_base + j2 * 16;
                int cb = (2 * s + bcb_add) ^ (r & 7);
                ldsm4(bf[j2], bchunk + (uint32_t)(r * 128 + cb * 16));
            }
#pragma unroll
            for (int i = 0; i < 4; i++)
#pragma unroll
                for (int j = 0; j < 8; j++)
                    mma_f16(acc[i][j], af[i], &bf[j >> 1][(j & 1) * 2]);
        }

        if ((c & 3) == 3) {
            // epilogue for m-tile c>>2 (regs+gmem only; no smem)
            int row0 = rowbase + (c >> 2) * MT;
#pragma unroll
            for (int j = 0; j < 8; j++) {
                int col = n0 + wn + j * 8 + cpair;
                float b0 = __ldg(bias + col), b1 = __ldg(bias + col + 1);
#pragma unroll
                for (int i = 0; i < 4; i++) {
                    int r = row0 + wm + i * 16 + g;
                    float v0 = fmaxf(acc[i][j][0] + b0, 0.0f);
                    float v1 = fmaxf(acc[i][j][1] + b1, 0.0f);
                    float v2 = fmaxf(acc[i][j][2] + b0, 0.0f);
                    float v3 = fmaxf(acc[i][j][3] + b1, 0.0f);
                    *reinterpret_cast<__half2*>(C + (size_t)r * D_H + col)
                        = __floats2half2_rn(v0, v1);
                    *reinterpret_cast<__half2*>(C + (size_t)(r + 8) * D_H + col)
                        = __floats2half2_rn(v2, v3);
                }
            }
#pragma unroll
            for (int i = 0; i < 4; i++)
#pragma unroll
                for (int j = 0; j < 8; j++)
#pragma unroll
                    for (int cc = 0; cc < 4; cc++) acc[i][j][cc] = 0.0f;
        }
        __syncthreads();
    }
}

// ===========================================================================
// GEMM2 (exact R12 champion): 2-stage, 2 syncs/chunk, fp16 out.
// ===========================================================================
#define STAGE_BYTES (2 * TILE_BYTES)     // 32768
#define SM_TOTAL    (2 * STAGE_BYTES)    // 65536

__global__ void __launch_bounds__(128, 2) tc_gemm(
    const __half* __restrict__ A, const __half* __restrict__ Bt,
    const float* __restrict__ bias, __half* __restrict__ C,
    int K, int ldc, int relu)
{
    extern __shared__ char smem[];
    uint32_t sb = smem_u32(smem);
    const int tid = threadIdx.x, wid = tid >> 5, lane = tid & 31;
    const int row0 = blockIdx.y * MT;
    const int n0   = blockIdx.x * NTT;

    const uint32_t aoff[2] = { sb,              sb + STAGE_BYTES };
    const uint32_t boff[2] = { sb + TILE_BYTES, sb + STAGE_BYTES + TILE_BYTES };

    const int lr = tid >> 3;
    const int lc = tid & 7;
    const __half* Abase = A  + (size_t)row0 * K + lc * 8;
    const __half* Bbase = Bt + (size_t)n0   * K + lc * 8;

    auto load_chunk = [&](int kt, int bi) {
        const __half* Ap = Abase + kt * KC;
        const __half* Bp = Bbase + kt * KC;
#pragma unroll
        for (int i = 0; i < 8; i++) {
            int r = lr + i * 16;
            uint32_t so = (uint32_t)(r * 128 + ((lc ^ (r & 7)) << 4));
            cpa16(aoff[bi] + so, Ap + (size_t)r * K);
            cpa16(boff[bi] + so, Bp + (size_t)r * K);
        }
        asm volatile("cp.async.commit_group;" ::: "memory");
    };

    const int wm = (wid >> 1) * 64;
    const int wn = (wid & 1) * 64;
    const int q = lane >> 3;
    const int arow_base = wm + (q & 1) * 8 + (lane & 7);
    const int acb_add   = q >> 1;
    const int brow_base = wn + (q >> 1) * 8 + (lane & 7);
    const int bcb_add   = q & 1;

    float acc[4][8][4];
#pragma unroll
    for (int i = 0; i < 4; i++)
#pragma unroll
        for (int j = 0; j < 8; j++)
#pragma unroll
            for (int c = 0; c < 4; c++) acc[i][j][c] = 0.0f;

    const int nkt = K / KC;
    load_chunk(0, 0);

    for (int kt = 0; kt < nkt; kt++) {
        int b = kt & 1;
        if (kt + 1 < nkt) {
            load_chunk(kt + 1, b ^ 1);
            asm volatile("cp.async.wait_group 1;" ::: "memory");
        } else {
            asm volatile("cp.async.wait_group 0;" ::: "memory");
        }
        __syncthreads();

#pragma unroll
        for (int s = 0; s < 4; s++) {
            uint32_t af[4][4], bf[4][4];
#pragma unroll
            for (int i = 0; i < 4; i++) {
                int r = arow_base + i * 16;
                int cb = (2 * s + acb_add) ^ (r & 7);
                ldsm4(af[i], aoff[b] + (uint32_t)(r * 128 + cb * 16));
            }
#pragma unroll
            for (int j2 = 0; j2 < 4; j2++) {
                int r = brow_base + j2 * 16;
                int cb = (2 * s + bcb_add) ^ (r & 7);
                ldsm4(bf[j2], boff[b] + (uint32_t)(r * 128 + cb * 16));
            }
#pragma unroll
            for (int i = 0; i < 4; i++)
#pragma unroll
                for (int j = 0; j < 8; j++)
                    mma_f16(acc[i][j], af[i], &bf[j >> 1][(j & 1) * 2]);
        }
        __syncthreads();
    }

    const int g = lane >> 2, cpair = (lane & 3) * 2;
#pragma unroll
    for (int j = 0; j < 8; j++) {
        int col = n0 + wn + j * 8 + cpair;
        float b0 = __ldg(bias + col), b1 = __ldg(bias + col + 1);
#pragma unroll
        for (int i = 0; i < 4; i++) {
            int r = row0 + wm + i * 16 + g;
            float v0 = acc[i][j][0] + b0, v1 = acc[i][j][1] + b1;
            float v2 = acc[i][j][2] + b0, v3 = acc[i][j][3] + b1;
            if (relu) {
                v0 = fmaxf(v0, 0.0f); v1 = fmaxf(v1, 0.0f);
                v2 = fmaxf(v2, 0.0f); v3 = fmaxf(v3, 0.0f);
            }
            *reinterpret_cast<__half2*>(C + (size_t)r * ldc + col)
                = __floats2half2_rn(v0, v1);
            *reinterpret_cast<__half2*>(C + (size_t)(r + 8) * ldc + col)
                = __floats2half2_rn(v2, v3);
        }
    }
}

// ---------------------------------------------------------------------------
// Weight transpose to fp16: WT[c][r] = h(W[r][c])
// ---------------------------------------------------------------------------
__global__ __launch_bounds__(256) void transpose_kernel(
    const float* __restrict__ W, __half* __restrict__ WT, int R, int Cn)
{
    __shared__ float t[32][33];
    int bx = blockIdx.x * 32, by = blockIdx.y * 32;
    int x = threadIdx.x & 31, y = threadIdx.x >> 5;
#pragma unroll
    for (int i = 0; i < 32; i += 8)
        t[y + i][x] = W[(size_t)(by + y + i) * Cn + bx + x];
    __syncthreads();
#pragma unroll
    for (int i = 0; i < 32; i += 8)
        WT[(size_t)(bx + y + i) * R + by + x] = __float2half_rn(t[x][y + i]);
}

// ---------------------------------------------------------------------------
// LayerNorm (one warp/row), fp16 output
// ---------------------------------------------------------------------------
__global__ __launch_bounds__(256) void ln_kernel(
    const float* __restrict__ state, const float* __restrict__ nbrs,
    const float* __restrict__ gamma, const float* __restrict__ beta,
    __half* __restrict__ Xn, int B)
{
    int row  = blockIdx.x * 8 + (threadIdx.x >> 5);
    int lane = threadIdx.x & 31;
    const float* x = (row < B) ? state + (size_t)row * D_IN
                               : nbrs + (size_t)(row - B) * D_IN;
    float4 v0 = ((const float4*)x)[lane];
    float4 v1 = ((const float4*)x)[lane + 32];

    float s  = v0.x + v0.y + v0.z + v0.w + v1.x + v1.y + v1.z + v1.w;
    float ss = v0.x*v0.x + v0.y*v0.y + v0.z*v0.z + v0.w*v0.w
             + v1.x*v1.x + v1.y*v1.y + v1.z*v1.z + v1.w*v1.w;
#pragma unroll
    for (int o = 16; o; o >>= 1) {
        s  += __shfl_xor_sync(0xFFFFFFFFu, s,  o);
        ss += __shfl_xor_sync(0xFFFFFFFFu, ss, o);
    }
    float mu   = s * (1.0f / D_IN);
    float var  = ss * (1.0f / D_IN) - mu * mu;
    float rstd = rsqrtf(var + 1e-5f);

    float4 g0 = ((const float4*)gamma)[lane];
    float4 g1 = ((const float4*)gamma)[lane + 32];
    float4 be0 = ((const float4*)beta)[lane];
    float4 be1 = ((const float4*)beta)[lane + 32];

    __half2 h0 = __floats2half2_rn((v0.x - mu) * rstd * g0.x + be0.x,
                                   (v0.y - mu) * rstd * g0.y + be0.y);
    __half2 h1 = __floats2half2_rn((v0.z - mu) * rstd * g0.z + be0.z,
                                   (v0.w - mu) * rstd * g0.w + be0.w);
    __half2 h2 = __floats2half2_rn((v1.x - mu) * rstd * g1.x + be1.x,
                                   (v1.y - mu) * rstd * g1.y + be1.y);
    __half2 h3 = __floats2half2_rn((v1.z - mu) * rstd * g1.z + be1.z,
                                   (v1.w - mu) * rstd * g1.w + be1.w);

    __half* dst = Xn + (size_t)row * D_IN;
    uint2 w0, w1;
    w0.x = *(uint32_t*)&h0;  w0.y = *(uint32_t*)&h1;
    w1.x = *(uint32_t*)&h2;  w1.y = *(uint32_t*)&h3;
    ((uint2*)dst)[lane]      = w0;
    ((uint2*)(dst + 128))[lane] = w1;
}

// ---------------------------------------------------------------------------
// Attention aggregation (one warp/batch element), fp16 F, fp32 math/output.
// ---------------------------------------------------------------------------
__global__ __launch_bounds__(256) void attn_kernel(
    const __half* __restrict__ F, const float* __restrict__ aw,
    const float* __restrict__ ab_ptr, float* __restrict__ out, int B)
{
    int b    = blockIdx.x * 8 + (threadIdx.x >> 5);
    int lane = threadIdx.x & 31;
    float ab = ab_ptr[0];

    float4 w0 = ((const float4*)aw)[lane * 2];
    float4 w1 = ((const float4*)aw)[lane * 2 + 1];

    uint4 lv = ((const uint4*)(F + (size_t)b * D_OUT))[lane];
    float2 l0 = __half22float2(*(__half2*)&lv.x);
    float2 l1 = __half22float2(*(__half2*)&lv.y);
    float2 l2 = __half22float2(*(__half2*)&lv.z);
    float2 l3 = __half22float2(*(__half2*)&lv.w);

    uint4 nf[NB];
    float sc[NB];
#pragma unroll
    for (int n = 0; n < NB; n++) {
        nf[n] = ((const uint4*)(F + ((size_t)(1 + n) * B + b) * D_OUT))[lane];
        float2 a0 = __half22float2(*(__half2*)&nf[n].x);
        float2 a1 = __half22float2(*(__half2*)&nf[n].y);
        float2 a2 = __half22float2(*(__half2*)&nf[n].z);
        float2 a3 = __half22float2(*(__half2*)&nf[n].w);
        float d = a0.x * w0.x + a0.y * w0.y + a1.x * w0.z + a1.y * w0.w
                + a2.x * w1.x + a2.y * w1.y + a3.x * w1.z + a3.y * w1.w;
#pragma unroll
        for (int o = 16; o; o >>= 1) d += __shfl_xor_sync(0xFFFFFFFFu, d, o);
        sc[n] = d + ab;
    }

    float mx = sc[0];
#pragma unroll
    for (int n = 1; n < NB; n++) mx = fmaxf(mx, sc[n]);
    float se = 0.0f;
#pragma unroll
    for (int n = 0; n < NB; n++) { sc[n] = expf(sc[n] - mx); se += sc[n]; }
    float inv = 1.0f / se;

    float o0 = l0.x, o1 = l0.y, o2 = l1.x, o3 = l1.y;
    float o4 = l2.x, o5 = l2.y, o6 = l3.x, o7 = l3.y;
#pragma unroll
    for (int n = 0; n < NB; n++) {
        float wn = sc[n] * inv;
        float2 a0 = __half22float2(*(__half2*)&nf[n].x);
        float2 a1 = __half22float2(*(__half2*)&nf[n].y);
        float2 a2 = __half22float2(*(__half2*)&nf[n].z);
        float2 a3 = __half22float2(*(__half2*)&nf[n].w);
        o0 = fmaf(wn, a0.x, o0);  o1 = fmaf(wn, a0.y, o1);
        o2 = fmaf(wn, a1.x, o2);  o3 = fmaf(wn, a1.y, o3);
        o4 = fmaf(wn, a2.x, o4);  o5 = fmaf(wn, a2.y, o5);
        o6 = fmaf(wn, a3.x, o6);  o7 = fmaf(wn, a3.y, o7);
    }
    float* dst = out + (size_t)b * D_OUT;
    float4 r0 = { o0, o1, o2, o3 }, r1 = { o4, o5, o6, o7 };
    ((float4*)dst)[lane * 2]     = r0;
    ((float4*)dst)[lane * 2 + 1] = r1;
}

// ---------------------------------------------------------------------------
extern "C" void kernel_launch(void* const* d_in, const int* in_sizes, int n_in,
                              void* d_out, int out_size)
{
    const float* state = (const float*)d_in[0];
    const float* nbrs  = (const float*)d_in[1];
    const float* gamma = (const float*)d_in[2];
    const float* beta  = (const float*)d_in[3];
    const float* W1    = (const float*)d_in[4];
    const float* b1    = (const float*)d_in[5];
    const float* W2    = (const float*)d_in[6];
    const float* b2    = (const float*)d_in[7];
    const float* aw    = (const float*)d_in[8];
    const float* ab    = (const float*)d_in[9];
    float* out = (float*)d_out;

    int B = in_sizes[0] / D_IN;   // 32768
    int R = 9 * B;                // 294912

    __half *Xn, *H, *F, *W1T, *W2T;
    cudaGetSymbolAddress((void**)&Xn,  g_Xn);
    cudaGetSymbolAddress((void**)&H,   g_H);
    cudaGetSymbolAddress((void**)&F,   g_F);
    cudaGetSymbolAddress((void**)&W1T, g_W1T);
    cudaGetSymbolAddress((void**)&W2T, g_W2T);

    cudaFuncSetAttribute(tc_gemm1, cudaFuncAttributeMaxDynamicSharedMemorySize, G1_SMEM);
    cudaFuncSetAttribute(tc_gemm,  cudaFuncAttributeMaxDynamicSharedMemorySize, SM_TOTAL);

    transpose_kernel<<<dim3(D_H / 32,  D_IN / 32), 256>>>(W1, W1T, D_IN, D_H);
    transpose_kernel<<<dim3(D_OUT / 32, D_H / 32), 256>>>(W2, W2T, D_H, D_OUT);
    ln_kernel<<<R / 8, 256>>>(state, nbrs, gamma, beta, Xn, B);

    // H = h(relu(Xn @ W1 + b1)) — B-resident, 4 m-tiles per CTA
    tc_gemm1<<<dim3(D_H / NTT, R / (MSTEPS * MT)), 128, G1_SMEM>>>(Xn, W1T, b1, H);
    // F = h(H @ W2 + b2)
    tc_gemm<<<dim3(D_OUT / NTT, R / MT), 128, SM_TOTAL>>>(H, W2T, b2, F, D_H, D_OUT, 0);

    attn_kernel<<<B / 8, 256>>>(F, aw, ab, out, B);
}

// round 15
// speedup vs baseline: 1.0999x; 1.0174x over previous
#include <cuda_runtime.h>
#include <cuda_fp16.h>
#include <cstdint>
#include <math.h>

#define D_IN  256
#define D_H   512
#define D_OUT 256
#define NB    8
#define ROWS  (9 * 32768)

#define MT  128    // M tile (per m-step)
#define NTT 128    // CTA N tile
#define KC  64     // K chunk (halves) = 128 B/row
#define MSTEPS 4   // m-tiles per CTA (both GEMMs)

// Scratch (allocation-free rule)
__device__ __half g_Xn [(size_t)ROWS * D_IN];
__device__ __half g_H  [(size_t)ROWS * D_H];
__device__ __half g_F  [(size_t)ROWS * D_OUT];   // fp16 glue buffer
__device__ __half g_W1T[(size_t)D_H * D_IN];     // [N=512][K=256]
__device__ __half g_W2T[(size_t)D_OUT * D_H];    // [N=256][K=512]

// ---------------------------------------------------------------------------
__device__ __forceinline__ uint32_t smem_u32(const void* p) {
    uint32_t a;
    asm("{ .reg .u64 t; cvta.to.shared.u64 t, %1; cvt.u32.u64 %0, t; }" : "=r"(a) : "l"(p));
    return a;
}
__device__ __forceinline__ void cpa16(uint32_t s, const void* g) {
    asm volatile("cp.async.cg.shared.global [%0], [%1], 16;" :: "r"(s), "l"(g));
}
__device__ __forceinline__ void ldsm4(uint32_t* r, uint32_t addr) {
    asm volatile("ldmatrix.sync.aligned.m8n8.x4.shared.b16 {%0,%1,%2,%3}, [%4];"
                 : "=r"(r[0]), "=r"(r[1]), "=r"(r[2]), "=r"(r[3]) : "r"(addr));
}
__device__ __forceinline__ void mma_f16(float* c, const uint32_t* a, const uint32_t* b) {
    asm volatile("mma.sync.aligned.m16n8k16.row.col.f32.f16.f16.f32 "
                 "{%0,%1,%2,%3}, {%4,%5,%6,%7}, {%8,%9}, {%0,%1,%2,%3};"
                 : "+f"(c[0]), "+f"(c[1]), "+f"(c[2]), "+f"(c[3])
                 : "r"(a[0]), "r"(a[1]), "r"(a[2]), "r"(a[3]), "r"(b[0]), "r"(b[1]));
}

#define TILE_BYTES  (MT * KC * 2)        // 16384 (one 128-row x 128B tile)

// ===========================================================================
// GEMM1, B-resident multi-M (R14 champion): CTA = 4 m-tiles x 128 rows x
// 128 cols. smem: B resident 64 KB + A 2-stage ring 32 KB. 2 CTAs/SM.
// ===========================================================================
#define G1_SMEM (4 * TILE_BYTES + 2 * TILE_BYTES)   // 98304

__global__ void __launch_bounds__(128, 2) tc_gemm1(
    const __half* __restrict__ A, const __half* __restrict__ Bt,
    const float* __restrict__ bias, __half* __restrict__ C)
{
    extern __shared__ char smem[];
    uint32_t sb = smem_u32(smem);
    const int tid = threadIdx.x, wid = tid >> 5, lane = tid & 31;
    const int rowbase = blockIdx.y * (MSTEPS * MT);
    const int n0      = blockIdx.x * NTT;

    const uint32_t bres    = sb;                       // B: 4 chunks x 16 KB
    const uint32_t aoff[2] = { sb + 4 * TILE_BYTES, sb + 5 * TILE_BYTES };

    const int lr = tid >> 3;          // base row 0..15, stride 16
    const int lc = tid & 7;           // 16B block (8 halves)
    const __half* Bbase = Bt + (size_t)n0 * D_IN + lc * 8;
    const __half* Abase = A + (size_t)rowbase * D_IN + lc * 8;

    // resident B (one group)
    {
#pragma unroll
        for (int kt = 0; kt < 4; kt++) {
            const __half* Bp = Bbase + kt * KC;
#pragma unroll
            for (int i = 0; i < 8; i++) {
                int r = lr + i * 16;
                uint32_t so = (uint32_t)(r * 128 + ((lc ^ (r & 7)) << 4));
                cpa16(bres + kt * TILE_BYTES + so, Bp + (size_t)r * D_IN);
            }
        }
        asm volatile("cp.async.commit_group;" ::: "memory");
    }
    auto loadA = [&](int c, int bi) {   // chunk c: mt=c>>2, kt=c&3
        const __half* Ap = Abase + (size_t)(c >> 2) * MT * D_IN + (c & 3) * KC;
#pragma unroll
        for (int i = 0; i < 8; i++) {
            int r = lr + i * 16;
            uint32_t so = (uint32_t)(r * 128 + ((lc ^ (r & 7)) << 4));
            cpa16(aoff[bi] + so, Ap + (size_t)r * D_IN);
        }
        asm volatile("cp.async.commit_group;" ::: "memory");
    };
    loadA(0, 0);

    const int wm = (wid >> 1) * 64;
    const int wn = (wid & 1) * 64;
    const int q = lane >> 3;
    const int arow_base = wm + (q & 1) * 8 + (lane & 7);
    const int acb_add   = q >> 1;
    const int brow_base = wn + (q >> 1) * 8 + (lane & 7);
    const int bcb_add   = q & 1;
    const int g = lane >> 2, cpair = (lane & 3) * 2;

    float acc[4][8][4];
#pragma unroll
    for (int i = 0; i < 4; i++)
#pragma unroll
        for (int j = 0; j < 8; j++)
#pragma unroll
            for (int c = 0; c < 4; c++) acc[i][j][c] = 0.0f;

    const int NCH = MSTEPS * 4;       // 16 A-chunks
    for (int c = 0; c < NCH; c++) {
        int b = c & 1;
        if (c + 1 < NCH) {
            loadA(c + 1, b ^ 1);
            asm volatile("cp.async.wait_group 1;" ::: "memory");
        } else {
            asm volatile("cp.async.wait_group 0;" ::: "memory");
        }
        __syncthreads();

        const uint32_t bchunk = bres + (uint32_t)(c & 3) * TILE_BYTES;
#pragma unroll
        for (int s = 0; s < 4; s++) {
            uint32_t af[4][4], bf[4][4];
#pragma unroll
            for (int i = 0; i < 4; i++) {
                int r = arow_base + i * 16;
                int cb = (2 * s + acb_add) ^ (r & 7);
                ldsm4(af[i], aoff[b] + (uint32_t)(r * 128 + cb * 16));
            }
#pragma unroll
            for (int j2 = 0; j2 < 4; j2++) {
                int r = brow_base + j2 * 16;
                int cb = (2 * s + bcb_add) ^ (r & 7);
                ldsm4(bf[j2], bchunk + (uint32_t)(r * 128 + cb * 16));
            }
#pragma unroll
            for (int i = 0; i < 4; i++)
#pragma unroll
                for (int j = 0; j < 8; j++)
                    mma_f16(acc[i][j], af[i], &bf[j >> 1][(j & 1) * 2]);
        }

        if ((c & 3) == 3) {
            int row0 = rowbase + (c >> 2) * MT;
#pragma unroll
            for (int j = 0; j < 8; j++) {
                int col = n0 + wn + j * 8 + cpair;
                float b0 = __ldg(bias + col), b1 = __ldg(bias + col + 1);
#pragma unroll
                for (int i = 0; i < 4; i++) {
                    int r = row0 + wm + i * 16 + g;
                    float v0 = fmaxf(acc[i][j][0] + b0, 0.0f);
                    float v1 = fmaxf(acc[i][j][1] + b1, 0.0f);
                    float v2 = fmaxf(acc[i][j][2] + b0, 0.0f);
                    float v3 = fmaxf(acc[i][j][3] + b1, 0.0f);
                    *reinterpret_cast<__half2*>(C + (size_t)r * D_H + col)
                        = __floats2half2_rn(v0, v1);
                    *reinterpret_cast<__half2*>(C + (size_t)(r + 8) * D_H + col)
                        = __floats2half2_rn(v2, v3);
                }
            }
#pragma unroll
            for (int i = 0; i < 4; i++)
#pragma unroll
                for (int j = 0; j < 8; j++)
#pragma unroll
                    for (int cc = 0; cc < 4; cc++) acc[i][j][cc] = 0.0f;
        }
        __syncthreads();
    }
}

// ===========================================================================
// GEMM2 multi-M: CTA = 4 m-tiles x 128 rows x 128 cols over K=512.
// Streams A+B (B chunks re-read from L2 per m-tile; W2T is L2-resident).
// Same 2-stage/2-sync ring as R12; flat 32-chunk loop, epilogue each 8th.
// ===========================================================================
#define STAGE_BYTES (2 * TILE_BYTES)     // 32768
#define SM_TOTAL    (2 * STAGE_BYTES)    // 65536

__global__ void __launch_bounds__(128, 2) tc_gemm2(
    const __half* __restrict__ A, const __half* __restrict__ Bt,
    const float* __restrict__ bias, __half* __restrict__ C)
{
    extern __shared__ char smem[];
    uint32_t sb = smem_u32(smem);
    const int tid = threadIdx.x, wid = tid >> 5, lane = tid & 31;
    const int rowbase = blockIdx.y * (MSTEPS * MT);
    const int n0      = blockIdx.x * NTT;

    const uint32_t aoff[2] = { sb,              sb + STAGE_BYTES };
    const uint32_t boff[2] = { sb + TILE_BYTES, sb + STAGE_BYTES + TILE_BYTES };

    const int lr = tid >> 3;
    const int lc = tid & 7;
    const __half* Abase = A  + (size_t)rowbase * D_H + lc * 8;
    const __half* Bbase = Bt + (size_t)n0 * D_H + lc * 8;

    auto load_chunk = [&](int c, int bi) {   // c: mt=c>>3, kt=c&7
        const __half* Ap = Abase + (size_t)(c >> 3) * MT * D_H + (c & 7) * KC;
        const __half* Bp = Bbase + (c & 7) * KC;
#pragma unroll
        for (int i = 0; i < 8; i++) {
            int r = lr + i * 16;
            uint32_t so = (uint32_t)(r * 128 + ((lc ^ (r & 7)) << 4));
            cpa16(aoff[bi] + so, Ap + (size_t)r * D_H);
            cpa16(boff[bi] + so, Bp + (size_t)r * D_H);
        }
        asm volatile("cp.async.commit_group;" ::: "memory");
    };

    const int wm = (wid >> 1) * 64;
    const int wn = (wid & 1) * 64;
    const int q = lane >> 3;
    const int arow_base = wm + (q & 1) * 8 + (lane & 7);
    const int acb_add   = q >> 1;
    const int brow_base = wn + (q >> 1) * 8 + (lane & 7);
    const int bcb_add   = q & 1;
    const int g = lane >> 2, cpair = (lane & 3) * 2;

    float acc[4][8][4];
#pragma unroll
    for (int i = 0; i < 4; i++)
#pragma unroll
        for (int j = 0; j < 8; j++)
#pragma unroll
            for (int c = 0; c < 4; c++) acc[i][j][c] = 0.0f;

    const int NCH = MSTEPS * 8;       // 32 chunks
    load_chunk(0, 0);

    for (int c = 0; c < NCH; c++) {
        int b = c & 1;
        if (c + 1 < NCH) {
            load_chunk(c + 1, b ^ 1);
            asm volatile("cp.async.wait_group 1;" ::: "memory");
        } else {
            asm volatile("cp.async.wait_group 0;" ::: "memory");
        }
        __syncthreads();

#pragma unroll
        for (int s = 0; s < 4; s++) {
            uint32_t af[4][4], bf[4][4];
#pragma unroll
            for (int i = 0; i < 4; i++) {
                int r = arow_base + i * 16;
                int cb = (2 * s + acb_add) ^ (r & 7);
                ldsm4(af[i], aoff[b] + (uint32_t)(r * 128 + cb * 16));
            }
#pragma unroll
            for (int j2 = 0; j2 < 4; j2++) {
                int r = brow_base + j2 * 16;
                int cb = (2 * s + bcb_add) ^ (r & 7);
                ldsm4(bf[j2], boff[b] + (uint32_t)(r * 128 + cb * 16));
            }
#pragma unroll
            for (int i = 0; i < 4; i++)
#pragma unroll
                for (int j = 0; j < 8; j++)
                    mma_f16(acc[i][j], af[i], &bf[j >> 1][(j & 1) * 2]);
        }

        if ((c & 7) == 7) {
            int row0 = rowbase + (c >> 3) * MT;
#pragma unroll
            for (int j = 0; j < 8; j++) {
                int col = n0 + wn + j * 8 + cpair;
                float b0 = __ldg(bias + col), b1 = __ldg(bias + col + 1);
#pragma unroll
                for (int i = 0; i < 4; i++) {
                    int r = row0 + wm + i * 16 + g;
                    float v0 = acc[i][j][0] + b0, v1 = acc[i][j][1] + b1;
                    float v2 = acc[i][j][2] + b0, v3 = acc[i][j][3] + b1;
                    *reinterpret_cast<__half2*>(C + (size_t)r * D_OUT + col)
                        = __floats2half2_rn(v0, v1);
                    *reinterpret_cast<__half2*>(C + (size_t)(r + 8) * D_OUT + col)
                        = __floats2half2_rn(v2, v3);
                }
            }
#pragma unroll
            for (int i = 0; i < 4; i++)
#pragma unroll
                for (int j = 0; j < 8; j++)
#pragma unroll
                    for (int cc = 0; cc < 4; cc++) acc[i][j][cc] = 0.0f;
        }
        __syncthreads();
    }
}

// ---------------------------------------------------------------------------
// Fused weight transposes (one launch): z=0 -> W1 (256x512), z=1 -> W2 (512x256)
// ---------------------------------------------------------------------------
__global__ __launch_bounds__(256) void transpose_both_kernel(
    const float* __restrict__ W1, __half* __restrict__ W1T,
    const float* __restrict__ W2, __half* __restrict__ W2T)
{
    const float* W;  __half* WT;  int R, Cn;
    if (blockIdx.z == 0) { W = W1; WT = W1T; R = D_IN; Cn = D_H; }
    else                 { W = W2; WT = W2T; R = D_H;  Cn = D_OUT; }
    int bx = blockIdx.x * 32, by = blockIdx.y * 32;
    if (bx >= Cn || by >= R) return;

    __shared__ float t[32][33];
    int x = threadIdx.x & 31, y = threadIdx.x >> 5;
#pragma unroll
    for (int i = 0; i < 32; i += 8)
        t[y + i][x] = W[(size_t)(by + y + i) * Cn + bx + x];
    __syncthreads();
#pragma unroll
    for (int i = 0; i < 32; i += 8)
        WT[(size_t)(bx + y + i) * R + by + x] = __float2half_rn(t[x][y + i]);
}

// ---------------------------------------------------------------------------
// LayerNorm (one warp/row), fp16 output
// ---------------------------------------------------------------------------
__global__ __launch_bounds__(256) void ln_kernel(
    const float* __restrict__ state, const float* __restrict__ nbrs,
    const float* __restrict__ gamma, const float* __restrict__ beta,
    __half* __restrict__ Xn, int B)
{
    int row  = blockIdx.x * 8 + (threadIdx.x >> 5);
    int lane = threadIdx.x & 31;
    const float* x = (row < B) ? state + (size_t)row * D_IN
                               : nbrs + (size_t)(row - B) * D_IN;
    float4 v0 = ((const float4*)x)[lane];
    float4 v1 = ((const float4*)x)[lane + 32];

    float s  = v0.x + v0.y + v0.z + v0.w + v1.x + v1.y + v1.z + v1.w;
    float ss = v0.x*v0.x + v0.y*v0.y + v0.z*v0.z + v0.w*v0.w
             + v1.x*v1.x + v1.y*v1.y + v1.z*v1.z + v1.w*v1.w;
#pragma unroll
    for (int o = 16; o; o >>= 1) {
        s  += __shfl_xor_sync(0xFFFFFFFFu, s,  o);
        ss += __shfl_xor_sync(0xFFFFFFFFu, ss, o);
    }
    float mu   = s * (1.0f / D_IN);
    float var  = ss * (1.0f / D_IN) - mu * mu;
    float rstd = rsqrtf(var + 1e-5f);

    float4 g0 = ((const float4*)gamma)[lane];
    float4 g1 = ((const float4*)gamma)[lane + 32];
    float4 be0 = ((const float4*)beta)[lane];
    float4 be1 = ((const float4*)beta)[lane + 32];

    __half2 h0 = __floats2half2_rn((v0.x - mu) * rstd * g0.x + be0.x,
                                   (v0.y - mu) * rstd * g0.y + be0.y);
    __half2 h1 = __floats2half2_rn((v0.z - mu) * rstd * g0.z + be0.z,
                                   (v0.w - mu) * rstd * g0.w + be0.w);
    __half2 h2 = __floats2half2_rn((v1.x - mu) * rstd * g1.x + be1.x,
                                   (v1.y - mu) * rstd * g1.y + be1.y);
    __half2 h3 = __floats2half2_rn((v1.z - mu) * rstd * g1.z + be1.z,
                                   (v1.w - mu) * rstd * g1.w + be1.w);

    __half* dst = Xn + (size_t)row * D_IN;
    uint2 w0, w1;
    w0.x = *(uint32_t*)&h0;  w0.y = *(uint32_t*)&h1;
    w1.x = *(uint32_t*)&h2;  w1.y = *(uint32_t*)&h3;
    ((uint2*)dst)[lane]      = w0;
    ((uint2*)(dst + 128))[lane] = w1;
}

// ---------------------------------------------------------------------------
// Attention aggregation (one warp/batch element), fp16 F, fp32 math/output.
// ---------------------------------------------------------------------------
__global__ __launch_bounds__(256) void attn_kernel(
    const __half* __restrict__ F, const float* __restrict__ aw,
    const float* __restrict__ ab_ptr, float* __restrict__ out, int B)
{
    int b    = blockIdx.x * 8 + (threadIdx.x >> 5);
    int lane = threadIdx.x & 31;
    float ab = ab_ptr[0];

    float4 w0 = ((const float4*)aw)[lane * 2];
    float4 w1 = ((const float4*)aw)[lane * 2 + 1];

    uint4 lv = ((const uint4*)(F + (size_t)b * D_OUT))[lane];
    float2 l0 = __half22float2(*(__half2*)&lv.x);
    float2 l1 = __half22float2(*(__half2*)&lv.y);
    float2 l2 = __half22float2(*(__half2*)&lv.z);
    float2 l3 = __half22float2(*(__half2*)&lv.w);

    uint4 nf[NB];
    float sc[NB];
#pragma unroll
    for (int n = 0; n < NB; n++) {
        nf[n] = ((const uint4*)(F + ((size_t)(1 + n) * B + b) * D_OUT))[lane];
        float2 a0 = __half22float2(*(__half2*)&nf[n].x);
        float2 a1 = __half22float2(*(__half2*)&nf[n].y);
        float2 a2 = __half22float2(*(__half2*)&nf[n].z);
        float2 a3 = __half22float2(*(__half2*)&nf[n].w);
        float d = a0.x * w0.x + a0.y * w0.y + a1.x * w0.z + a1.y * w0.w
                + a2.x * w1.x + a2.y * w1.y + a3.x * w1.z + a3.y * w1.w;
#pragma unroll
        for (int o = 16; o; o >>= 1) d += __shfl_xor_sync(0xFFFFFFFFu, d, o);
        sc[n] = d + ab;
    }

    float mx = sc[0];
#pragma unroll
    for (int n = 1; n < NB; n++) mx = fmaxf(mx, sc[n]);
    float se = 0.0f;
#pragma unroll
    for (int n = 0; n < NB; n++) { sc[n] = expf(sc[n] - mx); se += sc[n]; }
    float inv = 1.0f / se;

    float o0 = l0.x, o1 = l0.y, o2 = l1.x, o3 = l1.y;
    float o4 = l2.x, o5 = l2.y, o6 = l3.x, o7 = l3.y;
#pragma unroll
    for (int n = 0; n < NB; n++) {
        float wn = sc[n] * inv;
        float2 a0 = __half22float2(*(__half2*)&nf[n].x);
        float2 a1 = __half22float2(*(__half2*)&nf[n].y);
        float2 a2 = __half22float2(*(__half2*)&nf[n].z);
        float2 a3 = __half22float2(*(__half2*)&nf[n].w);
        o0 = fmaf(wn, a0.x, o0);  o1 = fmaf(wn, a0.y, o1);
        o2 = fmaf(wn, a1.x, o2);  o3 = fmaf(wn, a1.y, o3);
        o4 = fmaf(wn, a2.x, o4);  o5 = fmaf(wn, a2.y, o5);
        o6 = fmaf(wn, a3.x, o6);  o7 = fmaf(wn, a3.y, o7);
    }
    float* dst = out + (size_t)b * D_OUT;
    float4 r0 = { o0, o1, o2, o3 }, r1 = { o4, o5, o6, o7 };
    ((float4*)dst)[lane * 2]     = r0;
    ((float4*)dst)[lane * 2 + 1] = r1;
}

// ---------------------------------------------------------------------------
extern "C" void kernel_launch(void* const* d_in, const int* in_sizes, int n_in,
                              void* d_out, int out_size)
{
    const float* state = (const float*)d_in[0];
    const float* nbrs  = (const float*)d_in[1];
    const float* gamma = (const float*)d_in[2];
    const float* beta  = (const float*)d_in[3];
    const float* W1    = (const float*)d_in[4];
    const float* b1    = (const float*)d_in[5];
    const float* W2    = (const float*)d_in[6];
    const float* b2    = (const float*)d_in[7];
    const float* aw    = (const float*)d_in[8];
    const float* ab    = (const float*)d_in[9];
    float* out = (float*)d_out;

    int B = in_sizes[0] / D_IN;   // 32768
    int R = 9 * B;                // 294912

    __half *Xn, *H, *F, *W1T, *W2T;
    cudaGetSymbolAddress((void**)&Xn,  g_Xn);
    cudaGetSymbolAddress((void**)&H,   g_H);
    cudaGetSymbolAddress((void**)&F,   g_F);
    cudaGetSymbolAddress((void**)&W1T, g_W1T);
    cudaGetSymbolAddress((void**)&W2T, g_W2T);

    cudaFuncSetAttribute(tc_gemm1, cudaFuncAttributeMaxDynamicSharedMemorySize, G1_SMEM);
    cudaFuncSetAttribute(tc_gemm2, cudaFuncAttributeMaxDynamicSharedMemorySize, SM_TOTAL);

    transpose_both_kernel<<<dim3(16, 16, 2), 256>>>(W1, W1T, W2, W2T);
    ln_kernel<<<R / 8, 256>>>(state, nbrs, gamma, beta, Xn, B);

    // H = h(relu(Xn @ W1 + b1)) — B-resident, 4 m-tiles per CTA
    tc_gemm1<<<dim3(D_H / NTT, R / (MSTEPS * MT)), 128, G1_SMEM>>>(Xn, W1T, b1, H);
    // F = h(H @ W2 + b2) — 4 m-tiles per CTA, B from L2
    tc_gemm2<<<dim3(D_OUT / NTT, R / (MSTEPS * MT)), 128, SM_TOTAL>>>(H, W2T, b2, F);

    attn_kernel<<<B / 8, 256>>>(F, aw, ab, out, B);
}